// round 13
// baseline (speedup 1.0000x reference)
#include <cuda_runtime.h>
#include <cuda_fp16.h>
#include <math.h>
#include <stdint.h>

#define D_MODEL 1024
#define D_FF    2048
#define NE      8
#define TMAX    2048

#define BK 32
#define STRA 80                       // A smem row stride bytes (128 rows)
#define STRB2 144                     // fused-GU B row stride (64 cols fp16)
#define B2_SZ (32 * STRB2)            // 4608
#define A_SZ (128 * STRA)             // 10240
#define STAGE_GU (A_SZ + 2 * B2_SZ)   // 19456 (A | Bg | Bu)
#define GU_DYN (2 * STAGE_GU)         // 38912
#define STRB 272                      // dn B row stride (128 cols fp16)
#define B_SZ (32 * STRB)              // 8704
#define STAGE_DN (A_SZ + B_SZ)        // 18944 (A | B)
#define DN_DYN (2 * STAGE_DN)         // 37888

// -------- device scratch (static; no cudaMalloc allowed) --------
__device__ int      g_count[NE];
__device__ double   g_probsum[NE];
__device__ int      g_tok[NE * TMAX];
__device__ float    g_wt[NE * TMAX];
// fp16 copies (uint4-typed for 16B-aligned vector access)
__device__ uint4    g_Wg16[(size_t)NE * D_MODEL * D_FF / 8];
__device__ uint4    g_Wu16[(size_t)NE * D_MODEL * D_FF / 8];
__device__ uint4    g_Wd16[(size_t)NE * D_FF * D_MODEL / 8];
__device__ uint4    g_x16[(size_t)TMAX * D_MODEL / 8];
__device__ uint4    g_Hp4[(size_t)NE * TMAX * D_FF / 8];   // fp16 h

// ---------------- helpers ----------------
__device__ __forceinline__ uint32_t smem_u32(const void* p) {
    uint32_t a;
    asm("{ .reg .u64 t; cvta.to.shared.u64 t, %1; cvt.u32.u64 %0, t; }" : "=r"(a) : "l"(p));
    return a;
}
__device__ __forceinline__ uint32_t cvt2(float f0, float f1) {
    __half2 h = __floats2half2_rn(f0, f1);
    return *reinterpret_cast<uint32_t*>(&h);
}
__device__ __forceinline__ void ldsm_x4(uint32_t* r, uint32_t addr) {
    asm volatile("ldmatrix.sync.aligned.m8n8.x4.shared.b16 {%0,%1,%2,%3}, [%4];"
                 : "=r"(r[0]), "=r"(r[1]), "=r"(r[2]), "=r"(r[3]) : "r"(addr));
}
__device__ __forceinline__ void ldsm_x4t(uint32_t* r, uint32_t addr) {
    asm volatile("ldmatrix.sync.aligned.m8n8.x4.trans.shared.b16 {%0,%1,%2,%3}, [%4];"
                 : "=r"(r[0]), "=r"(r[1]), "=r"(r[2]), "=r"(r[3]) : "r"(addr));
}
__device__ __forceinline__ void mma16816(float* c, const uint32_t* a, const uint32_t* b) {
    asm volatile("mma.sync.aligned.m16n8k16.row.col.f32.f16.f16.f32 "
                 "{%0,%1,%2,%3}, {%4,%5,%6,%7}, {%8,%9}, {%0,%1,%2,%3};"
                 : "+f"(c[0]), "+f"(c[1]), "+f"(c[2]), "+f"(c[3])
                 : "r"(a[0]), "r"(a[1]), "r"(a[2]), "r"(a[3]), "r"(b[0]), "r"(b[1]));
}

// ---------------------------------------------------------------------------
__global__ void zero_kernel() {
    int i = threadIdx.x;
    if (i < NE) { g_count[i] = 0; g_probsum[i] = 0.0; }
}

// fp32 -> fp16 streaming converter: 8 floats per thread.
__global__ __launch_bounds__(256)
void cvt_kernel(const float4* __restrict__ src, uint4* __restrict__ dst) {
    size_t i = (size_t)blockIdx.x * 256 + threadIdx.x;
    float4 a = src[2 * i], b = src[2 * i + 1];
    dst[i] = make_uint4(cvt2(a.x, a.y), cvt2(a.z, a.w),
                        cvt2(b.x, b.y), cvt2(b.z, b.w));
}

__global__ void router_kernel(const float* __restrict__ x,
                              const float* __restrict__ gw,
                              const float* __restrict__ gb) {
    int t    = blockIdx.x;
    int warp = threadIdx.x >> 5;
    int lane = threadIdx.x & 31;
    __shared__ float logits[NE];

    const float* xr = x + (size_t)t * D_MODEL;
    const float* w  = gw + warp * D_MODEL;
    float s = 0.f;
    for (int i = lane; i < D_MODEL; i += 32) s += xr[i] * w[i];
    #pragma unroll
    for (int o = 16; o > 0; o >>= 1) s += __shfl_down_sync(0xffffffff, s, o);
    if (lane == 0) logits[warp] = s + gb[warp];
    __syncthreads();

    if (threadIdx.x == 0) {
        float p[NE];
        float mx = -1e30f;
        #pragma unroll
        for (int e = 0; e < NE; e++) mx = fmaxf(mx, logits[e]);
        float sum = 0.f;
        #pragma unroll
        for (int e = 0; e < NE; e++) { p[e] = expf(logits[e] - mx); sum += p[e]; }
        float inv = 1.f / sum;
        #pragma unroll
        for (int e = 0; e < NE; e++) {
            p[e] *= inv;
            atomicAdd(&g_probsum[e], (double)p[e]);
        }
        int i0 = 0;
        #pragma unroll
        for (int e = 1; e < NE; e++) if (p[e] > p[i0]) i0 = e;
        int i1 = -1;
        #pragma unroll
        for (int e = 0; e < NE; e++) {
            if (e == i0) continue;
            if (i1 < 0 || p[e] > p[i1]) i1 = e;
        }
        float v0 = p[i0], v1 = p[i1];
        float inv2 = 1.f / (v0 + v1);
        int s0 = atomicAdd(&g_count[i0], 1);
        g_tok[i0 * TMAX + s0] = t;  g_wt[i0 * TMAX + s0] = v0 * inv2;
        int s1 = atomicAdd(&g_count[i1], 1);
        g_tok[i1 * TMAX + s1] = t;  g_wt[i1 * TMAX + s1] = v1 * inv2;
    }
}

__global__ void loss_kernel(float* __restrict__ out_loss, int T) {
    if (threadIdx.x == 0) {
        const double ideal = 1.0 / NE;
        double l = 0.0;
        #pragma unroll
        for (int e = 0; e < NE; e++) {
            double mp = g_probsum[e] / (double)T + 1e-9;
            l += ideal * (log(ideal) - log(mp));
        }
        *out_loss = (float)l;
    }
}

// ---------------------------------------------------------------------------
// Fused GU: CTA computes 128x64 tile of BOTH G and U (all operands fp16,
// pre-converted), epilogue does silu(g)*u in-register, writes fp16 Hp.
// Warp grid 4(m) x 2(n), warptile 32x32 per matrix.
__global__ __launch_bounds__(256, 2)
void gu_kernel(const float* __restrict__ bg, const float* __restrict__ bu) {
    int e = blockIdx.z;
    int n = g_count[e];
    int rowbase = blockIdx.y * 128;
    if (rowbase >= n) return;
    int colbase = blockIdx.x * 64;

    const uint32_t* Wg16 = (const uint32_t*)g_Wg16 + (size_t)e * D_MODEL * (D_FF / 2);
    const uint32_t* Wu16 = (const uint32_t*)g_Wu16 + (size_t)e * D_MODEL * (D_FF / 2);
    const uint32_t* X16  = (const uint32_t*)g_x16;
    uint32_t*       Hp   = (uint32_t*)g_Hp4 + (size_t)e * TMAX * (D_FF / 2);

    extern __shared__ char sm[];
    __shared__ int toks[128];
    uint32_t sbase = smem_u32(sm);

    int tid = threadIdx.x, lane = tid & 31, wid = tid >> 5;
    int wm = wid >> 1, wn = wid & 1;

    if (tid < 128) {
        int r = rowbase + tid;
        toks[tid] = g_tok[e * TMAX + (r < n ? r : n - 1)];
    }
    __syncthreads();

    int arow = tid & 127, apart = tid >> 7;      // A: 2 threads/row, 32B each
    int krow = tid >> 3,  kseg  = tid & 7;       // B: 8 threads/krow, 16B each

    uint4 aR0, aR1, bgR, buR;
    auto ldg = [&](int k0) {
        const uint32_t* xr = X16 + (size_t)toks[arow] * (D_MODEL / 2) + (k0 >> 1) + apart * 8;
        aR0 = *(const uint4*)xr;
        aR1 = *(const uint4*)(xr + 4);
        size_t bo = (size_t)(k0 + krow) * (D_FF / 2) + (colbase >> 1) + kseg * 4;
        bgR = *(const uint4*)(Wg16 + bo);
        buR = *(const uint4*)(Wu16 + bo);
    };
    auto sts = [&](int buf) {
        char* st = sm + buf * STAGE_GU;
        *(uint4*)(st + arow * STRA + apart * 32)      = aR0;
        *(uint4*)(st + arow * STRA + apart * 32 + 16) = aR1;
        *(uint4*)(st + A_SZ + krow * STRB2 + kseg * 16)         = bgR;
        *(uint4*)(st + A_SZ + B2_SZ + krow * STRB2 + kseg * 16) = buR;
    };

    float accG[2][4][4] = {}, accU[2][4][4] = {};
    int ar = lane & 15, ac = lane >> 4;          // A ldsm addr parts
    int kr = lane & 7,  sel = lane >> 3;         // B ldsm addr parts

    auto compute = [&](int buf) {
        uint32_t Ah  = sbase + buf * STAGE_GU;
        uint32_t BGh = Ah + A_SZ;
        uint32_t BUh = BGh + B2_SZ;
        #pragma unroll
        for (int ks = 0; ks < 2; ks++) {
            uint32_t ah[2][4], bgh[8], buh[8];
            #pragma unroll
            for (int mt = 0; mt < 2; mt++) {
                uint32_t off = (uint32_t)((wm * 32 + mt * 16 + ar) * STRA + (ks * 16 + ac * 8) * 2);
                ldsm_x4(ah[mt], Ah + off);
            }
            #pragma unroll
            for (int nt2 = 0; nt2 < 2; nt2++) {
                int rowk = ks * 16 + (sel & 1) * 8 + kr;
                int coln = wn * 32 + nt2 * 16 + (sel >> 1) * 8;
                uint32_t off = (uint32_t)(rowk * STRB2 + coln * 2);
                ldsm_x4t(&bgh[nt2 * 4], BGh + off);
                ldsm_x4t(&buh[nt2 * 4], BUh + off);
            }
            #pragma unroll
            for (int mt = 0; mt < 2; mt++)
                #pragma unroll
                for (int nt = 0; nt < 4; nt++) {
                    int bo = (nt >> 1) * 4 + (nt & 1) * 2;
                    mma16816(accG[mt][nt], ah[mt], &bgh[bo]);
                    mma16816(accU[mt][nt], ah[mt], &buh[bo]);
                }
        }
    };

    const int NIT = D_MODEL / BK;   // 32
    ldg(0); sts(0);
    for (int i = 0; i < NIT; i++) {
        __syncthreads();
        if (i + 1 < NIT) ldg((i + 1) * BK);
        compute(i & 1);
        if (i + 1 < NIT) sts((i + 1) & 1);
    }

    // epilogue: h = silu(g+bg)*(u+bu), write fp16 half2-packed Hp
    const float* bgp = bg + e * D_FF + colbase;
    const float* bup = bu + e * D_FF + colbase;
    #pragma unroll
    for (int mt = 0; mt < 2; mt++) {
        int r0 = rowbase + wm * 32 + mt * 16 + (lane >> 2);
        #pragma unroll
        for (int nt = 0; nt < 4; nt++) {
            int c = wn * 32 + nt * 8 + (lane & 3) * 2;
            float bg0 = bgp[c], bg1 = bgp[c + 1];
            float bu0 = bup[c], bu1 = bup[c + 1];
            #pragma unroll
            for (int half = 0; half < 2; half++) {
                int r = r0 + half * 8;
                if (r >= n) continue;
                float g0 = accG[mt][nt][half * 2]     + bg0;
                float g1 = accG[mt][nt][half * 2 + 1] + bg1;
                float u0 = accU[mt][nt][half * 2]     + bu0;
                float u1 = accU[mt][nt][half * 2 + 1] + bu1;
                float h0 = g0 / (1.f + __expf(-g0)) * u0;
                float h1 = g1 / (1.f + __expf(-g1)) * u1;
                Hp[(size_t)r * (D_FF / 2) + (colbase + c) / 2] = cvt2(h0, h1);
            }
        }
    }
}

// ---------------------------------------------------------------------------
// Down: out[t] += w * ( H @ Wd + bd ), all fp16 operands, split-K=2.
__global__ __launch_bounds__(256, 2)
void dn_kernel(const float* __restrict__ bd, float* __restrict__ out) {
    int e  = blockIdx.z >> 1;
    int kb = blockIdx.z & 1;
    int n = g_count[e];
    int rowbase = blockIdx.y * 128;
    if (rowbase >= n) return;
    int colbase = blockIdx.x * 128;
    int kbase = kb * (D_FF / 2);

    const uint32_t* Wd16 = (const uint32_t*)g_Wd16 + (size_t)e * D_FF * (D_MODEL / 2);
    const uint32_t* Hp   = (const uint32_t*)g_Hp4 + (size_t)e * TMAX * (D_FF / 2);

    extern __shared__ char sm[];
    uint32_t sbase = smem_u32(sm);

    int tid = threadIdx.x, lane = tid & 31, wid = tid >> 5;
    int wm = wid >> 2, wn = wid & 3;

    int arow = tid & 127, apart = tid >> 7;
    int krow = tid >> 3,  kseg  = tid & 7;
    int r_a = rowbase + arow; if (r_a >= n) r_a = n - 1;

    uint4 aR0, aR1, bR0, bR1;
    auto ldg = [&](int k0) {
        const uint32_t* hp = Hp + (size_t)r_a * (D_FF / 2) + ((kbase + k0) >> 1) + apart * 8;
        aR0 = *(const uint4*)hp;
        aR1 = *(const uint4*)(hp + 4);
        const uint32_t* wp = Wd16 + (size_t)(kbase + k0 + krow) * (D_MODEL / 2) + (colbase >> 1);
        bR0 = *(const uint4*)(wp + kseg * 4);
        bR1 = *(const uint4*)(wp + kseg * 4 + 32);
    };
    auto sts = [&](int buf) {
        char* st = sm + buf * STAGE_DN;
        *(uint4*)(st + arow * STRA + apart * 32)      = aR0;
        *(uint4*)(st + arow * STRA + apart * 32 + 16) = aR1;
        *(uint4*)(st + A_SZ + krow * STRB + kseg * 16)       = bR0;
        *(uint4*)(st + A_SZ + krow * STRB + kseg * 16 + 128) = bR1;
    };

    float acc[4][4][4] = {};
    int ar = lane & 15, ac = lane >> 4;
    int kr = lane & 7,  sel = lane >> 3;

    auto compute = [&](int buf) {
        uint32_t Ah = sbase + buf * STAGE_DN;
        uint32_t Bh = Ah + A_SZ;
        #pragma unroll
        for (int ks = 0; ks < 2; ks++) {
            uint32_t ah[4][4], bh[8];
            #pragma unroll
            for (int mt = 0; mt < 4; mt++) {
                uint32_t off = (uint32_t)((wm * 64 + mt * 16 + ar) * STRA + (ks * 16 + ac * 8) * 2);
                ldsm_x4(ah[mt], Ah + off);
            }
            #pragma unroll
            for (int nt2 = 0; nt2 < 2; nt2++) {
                int rowk = ks * 16 + (sel & 1) * 8 + kr;
                int coln = wn * 32 + nt2 * 16 + (sel >> 1) * 8;
                uint32_t off = (uint32_t)(rowk * STRB + coln * 2);
                ldsm_x4t(&bh[nt2 * 4], Bh + off);
            }
            #pragma unroll
            for (int mt = 0; mt < 4; mt++)
                #pragma unroll
                for (int nt = 0; nt < 4; nt++) {
                    const uint32_t* bhp = &bh[(nt >> 1) * 4 + (nt & 1) * 2];
                    mma16816(acc[mt][nt], ah[mt], bhp);
                }
        }
    };

    const int NIT = (D_FF / 2) / BK;   // 32
    ldg(0); sts(0);
    for (int i = 0; i < NIT; i++) {
        __syncthreads();
        if (i + 1 < NIT) ldg((i + 1) * BK);
        compute(i & 1);
        if (i + 1 < NIT) sts((i + 1) & 1);
    }

    // epilogue: + bd (kb==0 only), * combine weight, atomic scatter into out
    #pragma unroll
    for (int mt = 0; mt < 4; mt++) {
        int r0 = rowbase + wm * 64 + mt * 16 + (lane >> 2);
        #pragma unroll
        for (int nt = 0; nt < 4; nt++) {
            int c = colbase + wn * 32 + nt * 8 + (lane & 3) * 2;
            float b0 = 0.f, b1 = 0.f;
            if (kb == 0) { b0 = bd[e * D_MODEL + c]; b1 = bd[e * D_MODEL + c + 1]; }
            if (r0 < n) {
                int t = g_tok[e * TMAX + r0];
                float w = g_wt[e * TMAX + r0];
                atomicAdd(&out[(size_t)t * D_MODEL + c],     w * (acc[mt][nt][0] + b0));
                atomicAdd(&out[(size_t)t * D_MODEL + c + 1], w * (acc[mt][nt][1] + b1));
            }
            if (r0 + 8 < n) {
                int t = g_tok[e * TMAX + r0 + 8];
                float w = g_wt[e * TMAX + r0 + 8];
                atomicAdd(&out[(size_t)t * D_MODEL + c],     w * (acc[mt][nt][2] + b0));
                atomicAdd(&out[(size_t)t * D_MODEL + c + 1], w * (acc[mt][nt][3] + b1));
            }
        }
    }
}

// ---------------------------------------------------------------------------
extern "C" void kernel_launch(void* const* d_in, const int* in_sizes, int n_in,
                              void* d_out, int out_size) {
    const float* x  = (const float*)d_in[0];
    const float* gw = (const float*)d_in[1];
    const float* gb = (const float*)d_in[2];
    const float* Wg = (const float*)d_in[3];
    const float* bg = (const float*)d_in[4];
    const float* Wu = (const float*)d_in[5];
    const float* bu = (const float*)d_in[6];
    const float* Wd = (const float*)d_in[7];
    const float* bd = (const float*)d_in[8];
    float* out = (float*)d_out;

    int T = in_sizes[0] / D_MODEL;   // 2048

    cudaFuncSetAttribute(gu_kernel, cudaFuncAttributeMaxDynamicSharedMemorySize, GU_DYN);
    cudaFuncSetAttribute(dn_kernel, cudaFuncAttributeMaxDynamicSharedMemorySize, DN_DYN);

    void *pWg16, *pWu16, *pWd16, *px16;
    cudaGetSymbolAddress(&pWg16, g_Wg16);
    cudaGetSymbolAddress(&pWu16, g_Wu16);
    cudaGetSymbolAddress(&pWd16, g_Wd16);
    cudaGetSymbolAddress(&px16,  g_x16);

    cudaMemsetAsync(out, 0, (size_t)T * D_MODEL * sizeof(float));
    zero_kernel<<<1, 32>>>();
    router_kernel<<<T, 256>>>(x, gw, gb);
    if (out_size > T * D_MODEL) {
        loss_kernel<<<1, 32>>>(out + (size_t)T * D_MODEL, T);
    }
    // fp32 -> fp16 pre-conversion (8 floats/thread)
    const int WBLK = (int)((size_t)NE * D_MODEL * D_FF / (256 * 8));   // 8192
    const int XBLK = (int)((size_t)T * D_MODEL / (256 * 8));           // 1024
    cvt_kernel<<<WBLK, 256>>>((const float4*)Wg, (uint4*)pWg16);
    cvt_kernel<<<WBLK, 256>>>((const float4*)Wu, (uint4*)pWu16);
    cvt_kernel<<<WBLK, 256>>>((const float4*)Wd, (uint4*)pWd16);
    cvt_kernel<<<XBLK, 256>>>((const float4*)x,  (uint4*)px16);

    dim3 g1(D_FF / 64, TMAX / 128, NE);        // 32 x 16 x 8
    gu_kernel<<<g1, 256, GU_DYN>>>(bg, bu);
    dim3 g2(D_MODEL / 128, TMAX / 128, NE * 2); // 8 x 16 x 16 (split-K=2)
    dn_kernel<<<g2, 256, DN_DYN>>>(bd, out);
}

// round 15
// speedup vs baseline: 1.1104x; 1.1104x over previous
#include <cuda_runtime.h>
#include <cuda_fp16.h>
#include <math.h>
#include <stdint.h>

#define D_MODEL 1024
#define D_FF    2048
#define NE      8
#define TMAX    2048

#define BK 32
#define NSTAGE 3
#define STRA 80                       // A smem row stride bytes (128 rows)
#define STRB2 144                     // fused-GU B row stride (64 cols fp16)
#define B2_SZ (32 * STRB2)            // 4608
#define A_SZ (128 * STRA)             // 10240
#define STAGE_GU (A_SZ + 2 * B2_SZ)   // 19456 (A | Bg | Bu)
#define GU_DYN (NSTAGE * STAGE_GU)    // 58368
#define STRB 272                      // dn B row stride (128 cols fp16)
#define B_SZ (32 * STRB)              // 8704
#define STAGE_DN (A_SZ + B_SZ)        // 18944 (A | B)
#define DN_DYN (NSTAGE * STAGE_DN)    // 56832

// -------- device scratch (static; no cudaMalloc allowed) --------
__device__ int      g_count[NE];
__device__ double   g_probsum[NE];
__device__ int      g_tok[NE * TMAX];
__device__ float    g_wt[NE * TMAX];
__device__ uint4    g_Wg16[(size_t)NE * D_MODEL * D_FF / 8];
__device__ uint4    g_Wu16[(size_t)NE * D_MODEL * D_FF / 8];
__device__ uint4    g_Wd16[(size_t)NE * D_FF * D_MODEL / 8];
__device__ uint4    g_x16[(size_t)TMAX * D_MODEL / 8];
__device__ uint4    g_Hp4[(size_t)NE * TMAX * D_FF / 8];   // fp16 h

// ---------------- helpers ----------------
__device__ __forceinline__ uint32_t smem_u32(const void* p) {
    uint32_t a;
    asm("{ .reg .u64 t; cvta.to.shared.u64 t, %1; cvt.u32.u64 %0, t; }" : "=r"(a) : "l"(p));
    return a;
}
__device__ __forceinline__ uint32_t cvt2(float f0, float f1) {
    __half2 h = __floats2half2_rn(f0, f1);
    return *reinterpret_cast<uint32_t*>(&h);
}
__device__ __forceinline__ void cp16(uint32_t smem_dst, const void* gmem_src) {
    asm volatile("cp.async.cg.shared.global [%0], [%1], 16;"
                 :: "r"(smem_dst), "l"(gmem_src) : "memory");
}
#define CP_COMMIT() asm volatile("cp.async.commit_group;" ::: "memory")
#define CP_WAIT1()  asm volatile("cp.async.wait_group 1;" ::: "memory")
#define CP_WAIT0()  asm volatile("cp.async.wait_group 0;" ::: "memory")
__device__ __forceinline__ void ldsm_x4(uint32_t* r, uint32_t addr) {
    asm volatile("ldmatrix.sync.aligned.m8n8.x4.shared.b16 {%0,%1,%2,%3}, [%4];"
                 : "=r"(r[0]), "=r"(r[1]), "=r"(r[2]), "=r"(r[3]) : "r"(addr));
}
__device__ __forceinline__ void ldsm_x4t(uint32_t* r, uint32_t addr) {
    asm volatile("ldmatrix.sync.aligned.m8n8.x4.trans.shared.b16 {%0,%1,%2,%3}, [%4];"
                 : "=r"(r[0]), "=r"(r[1]), "=r"(r[2]), "=r"(r[3]) : "r"(addr));
}
__device__ __forceinline__ void mma16816(float* c, const uint32_t* a, const uint32_t* b) {
    asm volatile("mma.sync.aligned.m16n8k16.row.col.f32.f16.f16.f32 "
                 "{%0,%1,%2,%3}, {%4,%5,%6,%7}, {%8,%9}, {%0,%1,%2,%3};"
                 : "+f"(c[0]), "+f"(c[1]), "+f"(c[2]), "+f"(c[3])
                 : "r"(a[0]), "r"(a[1]), "r"(a[2]), "r"(a[3]), "r"(b[0]), "r"(b[1]));
}

// ---------------------------------------------------------------------------
__global__ void zero_kernel() {
    int i = threadIdx.x;
    if (i < NE) { g_count[i] = 0; g_probsum[i] = 0.0; }
}

// fp32 -> fp16 streaming converter: 8 floats per thread.
__global__ __launch_bounds__(256)
void cvt_kernel(const float4* __restrict__ src, uint4* __restrict__ dst) {
    size_t i = (size_t)blockIdx.x * 256 + threadIdx.x;
    float4 a = src[2 * i], b = src[2 * i + 1];
    dst[i] = make_uint4(cvt2(a.x, a.y), cvt2(a.z, a.w),
                        cvt2(b.x, b.y), cvt2(b.z, b.w));
}

__global__ void router_kernel(const float* __restrict__ x,
                              const float* __restrict__ gw,
                              const float* __restrict__ gb) {
    int t    = blockIdx.x;
    int warp = threadIdx.x >> 5;
    int lane = threadIdx.x & 31;
    __shared__ float logits[NE];

    const float* xr = x + (size_t)t * D_MODEL;
    const float* w  = gw + warp * D_MODEL;
    float s = 0.f;
    for (int i = lane; i < D_MODEL; i += 32) s += xr[i] * w[i];
    #pragma unroll
    for (int o = 16; o > 0; o >>= 1) s += __shfl_down_sync(0xffffffff, s, o);
    if (lane == 0) logits[warp] = s + gb[warp];
    __syncthreads();

    if (threadIdx.x == 0) {
        float p[NE];
        float mx = -1e30f;
        #pragma unroll
        for (int e = 0; e < NE; e++) mx = fmaxf(mx, logits[e]);
        float sum = 0.f;
        #pragma unroll
        for (int e = 0; e < NE; e++) { p[e] = expf(logits[e] - mx); sum += p[e]; }
        float inv = 1.f / sum;
        #pragma unroll
        for (int e = 0; e < NE; e++) {
            p[e] *= inv;
            atomicAdd(&g_probsum[e], (double)p[e]);
        }
        int i0 = 0;
        #pragma unroll
        for (int e = 1; e < NE; e++) if (p[e] > p[i0]) i0 = e;
        int i1 = -1;
        #pragma unroll
        for (int e = 0; e < NE; e++) {
            if (e == i0) continue;
            if (i1 < 0 || p[e] > p[i1]) i1 = e;
        }
        float v0 = p[i0], v1 = p[i1];
        float inv2 = 1.f / (v0 + v1);
        int s0 = atomicAdd(&g_count[i0], 1);
        g_tok[i0 * TMAX + s0] = t;  g_wt[i0 * TMAX + s0] = v0 * inv2;
        int s1 = atomicAdd(&g_count[i1], 1);
        g_tok[i1 * TMAX + s1] = t;  g_wt[i1 * TMAX + s1] = v1 * inv2;
    }
}

__global__ void loss_kernel(float* __restrict__ out_loss, int T) {
    if (threadIdx.x == 0) {
        const double ideal = 1.0 / NE;
        double l = 0.0;
        #pragma unroll
        for (int e = 0; e < NE; e++) {
            double mp = g_probsum[e] / (double)T + 1e-9;
            l += ideal * (log(ideal) - log(mp));
        }
        *out_loss = (float)l;
    }
}

// ---------------------------------------------------------------------------
// Fused GU: 128x64 tile of BOTH G and U, fp16 operands via cp.async 3-stage
// pipeline; epilogue silu(g)*u in-register -> fp16 Hp.
__global__ __launch_bounds__(256, 2)
void gu_kernel(const float* __restrict__ bg, const float* __restrict__ bu) {
    int e = blockIdx.z;
    int n = g_count[e];
    int rowbase = blockIdx.y * 128;
    if (rowbase >= n) return;
    int colbase = blockIdx.x * 64;

    const uint32_t* Wg16 = (const uint32_t*)g_Wg16 + (size_t)e * D_MODEL * (D_FF / 2);
    const uint32_t* Wu16 = (const uint32_t*)g_Wu16 + (size_t)e * D_MODEL * (D_FF / 2);
    const uint32_t* X16  = (const uint32_t*)g_x16;
    uint32_t*       Hp   = (uint32_t*)g_Hp4 + (size_t)e * TMAX * (D_FF / 2);

    extern __shared__ char sm[];
    __shared__ int toks[128];
    uint32_t sbase = smem_u32(sm);

    int tid = threadIdx.x, lane = tid & 31, wid = tid >> 5;
    int wm = wid >> 1, wn = wid & 1;

    if (tid < 128) {
        int r = rowbase + tid;
        toks[tid] = g_tok[e * TMAX + (r < n ? r : n - 1)];
    }
    __syncthreads();

    auto issue = [&](int k0, int buf) {
        uint32_t stu = sbase + buf * STAGE_GU;
        // A: 128 rows x 64B = 512 chunks of 16B
        #pragma unroll
        for (int it = 0; it < 2; it++) {
            int c = tid + it * 256;
            int row = c >> 2, seg = c & 3;
            const uint32_t* src = X16 + (size_t)toks[row] * (D_MODEL / 2) + (k0 >> 1) + seg * 4;
            cp16(stu + row * STRA + seg * 16, src);
        }
        // Bg/Bu: 32 rows x 128B = 256 chunks each
        {
            int row = tid >> 3, seg = tid & 7;
            size_t bo = (size_t)(k0 + row) * (D_FF / 2) + (colbase >> 1) + seg * 4;
            cp16(stu + A_SZ + row * STRB2 + seg * 16, Wg16 + bo);
            cp16(stu + A_SZ + B2_SZ + row * STRB2 + seg * 16, Wu16 + bo);
        }
        CP_COMMIT();
    };

    float accG[2][4][4] = {}, accU[2][4][4] = {};
    int ar = lane & 15, ac = lane >> 4;          // A ldsm addr parts
    int kr = lane & 7,  sel = lane >> 3;         // B ldsm addr parts

    auto compute = [&](int buf) {
        uint32_t Ah  = sbase + buf * STAGE_GU;
        uint32_t BGh = Ah + A_SZ;
        uint32_t BUh = BGh + B2_SZ;
        #pragma unroll
        for (int ks = 0; ks < 2; ks++) {
            uint32_t ah[2][4], bgh[8], buh[8];
            #pragma unroll
            for (int mt = 0; mt < 2; mt++) {
                uint32_t off = (uint32_t)((wm * 32 + mt * 16 + ar) * STRA + (ks * 16 + ac * 8) * 2);
                ldsm_x4(ah[mt], Ah + off);
            }
            #pragma unroll
            for (int nt2 = 0; nt2 < 2; nt2++) {
                int rowk = ks * 16 + (sel & 1) * 8 + kr;
                int coln = wn * 32 + nt2 * 16 + (sel >> 1) * 8;
                uint32_t off = (uint32_t)(rowk * STRB2 + coln * 2);
                ldsm_x4t(&bgh[nt2 * 4], BGh + off);
                ldsm_x4t(&buh[nt2 * 4], BUh + off);
            }
            #pragma unroll
            for (int mt = 0; mt < 2; mt++)
                #pragma unroll
                for (int nt = 0; nt < 4; nt++) {
                    int bo = (nt >> 1) * 4 + (nt & 1) * 2;
                    mma16816(accG[mt][nt], ah[mt], &bgh[bo]);
                    mma16816(accU[mt][nt], ah[mt], &buh[bo]);
                }
        }
    };

    const int NIT = D_MODEL / BK;   // 32
    issue(0, 0);
    issue(BK, 1);
    for (int i = 0; i < NIT; i++) {
        if (i + 1 < NIT) { CP_WAIT1(); } else { CP_WAIT0(); }  // drain fully on last iter
        __syncthreads();
        if (i + NSTAGE - 1 < NIT) issue((i + NSTAGE - 1) * BK, (i + NSTAGE - 1) % NSTAGE);
        compute(i % NSTAGE);
    }

    // epilogue: h = silu(g+bg)*(u+bu), write fp16 half2-packed Hp
    const float* bgp = bg + e * D_FF + colbase;
    const float* bup = bu + e * D_FF + colbase;
    #pragma unroll
    for (int mt = 0; mt < 2; mt++) {
        int r0 = rowbase + wm * 32 + mt * 16 + (lane >> 2);
        #pragma unroll
        for (int nt = 0; nt < 4; nt++) {
            int c = wn * 32 + nt * 8 + (lane & 3) * 2;
            float bg0 = bgp[c], bg1 = bgp[c + 1];
            float bu0 = bup[c], bu1 = bup[c + 1];
            #pragma unroll
            for (int half = 0; half < 2; half++) {
                int r = r0 + half * 8;
                if (r >= n) continue;
                float g0 = accG[mt][nt][half * 2]     + bg0;
                float g1 = accG[mt][nt][half * 2 + 1] + bg1;
                float u0 = accU[mt][nt][half * 2]     + bu0;
                float u1 = accU[mt][nt][half * 2 + 1] + bu1;
                float h0 = g0 / (1.f + __expf(-g0)) * u0;
                float h1 = g1 / (1.f + __expf(-g1)) * u1;
                Hp[(size_t)r * (D_FF / 2) + (colbase + c) / 2] = cvt2(h0, h1);
            }
        }
    }
}

// ---------------------------------------------------------------------------
// Down: out[t] += w * ( H @ Wd + bd ), fp16 via cp.async pipeline, split-K=2.
__global__ __launch_bounds__(256, 2)
void dn_kernel(const float* __restrict__ bd, float* __restrict__ out) {
    int e  = blockIdx.z >> 1;
    int kb = blockIdx.z & 1;
    int n = g_count[e];
    int rowbase = blockIdx.y * 128;
    if (rowbase >= n) return;
    int colbase = blockIdx.x * 128;
    int kbase = kb * (D_FF / 2);

    const uint32_t* Wd16 = (const uint32_t*)g_Wd16 + (size_t)e * D_FF * (D_MODEL / 2);
    const uint32_t* Hp   = (const uint32_t*)g_Hp4 + (size_t)e * TMAX * (D_FF / 2);

    extern __shared__ char sm[];
    uint32_t sbase = smem_u32(sm);

    int tid = threadIdx.x, lane = tid & 31, wid = tid >> 5;
    int wm = wid >> 2, wn = wid & 3;

    auto issue = [&](int k0, int buf) {
        uint32_t stu = sbase + buf * STAGE_DN;
        // A: 128 rows x 64B = 512 chunks
        #pragma unroll
        for (int it = 0; it < 2; it++) {
            int c = tid + it * 256;
            int row = c >> 2, seg = c & 3;
            int r = rowbase + row; if (r >= n) r = n - 1;
            const uint32_t* src = Hp + (size_t)r * (D_FF / 2) + ((kbase + k0) >> 1) + seg * 4;
            cp16(stu + row * STRA + seg * 16, src);
        }
        // B: 32 rows x 256B = 512 chunks
        #pragma unroll
        for (int it = 0; it < 2; it++) {
            int c = tid + it * 256;
            int row = c >> 4, seg = c & 15;
            const uint32_t* src = Wd16 + (size_t)(kbase + k0 + row) * (D_MODEL / 2) + (colbase >> 1) + seg * 4;
            cp16(stu + A_SZ + row * STRB + seg * 16, src);
        }
        CP_COMMIT();
    };

    float acc[4][4][4] = {};
    int ar = lane & 15, ac = lane >> 4;
    int kr = lane & 7,  sel = lane >> 3;

    auto compute = [&](int buf) {
        uint32_t Ah = sbase + buf * STAGE_DN;
        uint32_t Bh = Ah + A_SZ;
        #pragma unroll
        for (int ks = 0; ks < 2; ks++) {
            uint32_t ah[4][4], bh[8];
            #pragma unroll
            for (int mt = 0; mt < 4; mt++) {
                uint32_t off = (uint32_t)((wm * 64 + mt * 16 + ar) * STRA + (ks * 16 + ac * 8) * 2);
                ldsm_x4(ah[mt], Ah + off);
            }
            #pragma unroll
            for (int nt2 = 0; nt2 < 2; nt2++) {
                int rowk = ks * 16 + (sel & 1) * 8 + kr;
                int coln = wn * 32 + nt2 * 16 + (sel >> 1) * 8;
                uint32_t off = (uint32_t)(rowk * STRB + coln * 2);
                ldsm_x4t(&bh[nt2 * 4], Bh + off);
            }
            #pragma unroll
            for (int mt = 0; mt < 4; mt++)
                #pragma unroll
                for (int nt = 0; nt < 4; nt++) {
                    const uint32_t* bhp = &bh[(nt >> 1) * 4 + (nt & 1) * 2];
                    mma16816(acc[mt][nt], ah[mt], bhp);
                }
        }
    };

    const int NIT = (D_FF / 2) / BK;   // 32
    issue(0, 0);
    issue(BK, 1);
    for (int i = 0; i < NIT; i++) {
        if (i + 1 < NIT) { CP_WAIT1(); } else { CP_WAIT0(); }  // drain fully on last iter
        __syncthreads();
        if (i + NSTAGE - 1 < NIT) issue((i + NSTAGE - 1) * BK, (i + NSTAGE - 1) % NSTAGE);
        compute(i % NSTAGE);
    }

    // epilogue: + bd (kb==0 only), * combine weight, atomic scatter into out
    #pragma unroll
    for (int mt = 0; mt < 4; mt++) {
        int r0 = rowbase + wm * 64 + mt * 16 + (lane >> 2);
        #pragma unroll
        for (int nt = 0; nt < 4; nt++) {
            int c = colbase + wn * 32 + nt * 8 + (lane & 3) * 2;
            float b0 = 0.f, b1 = 0.f;
            if (kb == 0) { b0 = bd[e * D_MODEL + c]; b1 = bd[e * D_MODEL + c + 1]; }
            if (r0 < n) {
                int t = g_tok[e * TMAX + r0];
                float w = g_wt[e * TMAX + r0];
                atomicAdd(&out[(size_t)t * D_MODEL + c],     w * (acc[mt][nt][0] + b0));
                atomicAdd(&out[(size_t)t * D_MODEL + c + 1], w * (acc[mt][nt][1] + b1));
            }
            if (r0 + 8 < n) {
                int t = g_tok[e * TMAX + r0 + 8];
                float w = g_wt[e * TMAX + r0 + 8];
                atomicAdd(&out[(size_t)t * D_MODEL + c],     w * (acc[mt][nt][2] + b0));
                atomicAdd(&out[(size_t)t * D_MODEL + c + 1], w * (acc[mt][nt][3] + b1));
            }
        }
    }
}

// ---------------------------------------------------------------------------
extern "C" void kernel_launch(void* const* d_in, const int* in_sizes, int n_in,
                              void* d_out, int out_size) {
    const float* x  = (const float*)d_in[0];
    const float* gw = (const float*)d_in[1];
    const float* gb = (const float*)d_in[2];
    const float* Wg = (const float*)d_in[3];
    const float* bg = (const float*)d_in[4];
    const float* Wu = (const float*)d_in[5];
    const float* bu = (const float*)d_in[6];
    const float* Wd = (const float*)d_in[7];
    const float* bd = (const float*)d_in[8];
    float* out = (float*)d_out;

    int T = in_sizes[0] / D_MODEL;   // 2048

    cudaFuncSetAttribute(gu_kernel, cudaFuncAttributeMaxDynamicSharedMemorySize, GU_DYN);
    cudaFuncSetAttribute(dn_kernel, cudaFuncAttributeMaxDynamicSharedMemorySize, DN_DYN);

    void *pWg16, *pWu16, *pWd16, *px16;
    cudaGetSymbolAddress(&pWg16, g_Wg16);
    cudaGetSymbolAddress(&pWu16, g_Wu16);
    cudaGetSymbolAddress(&pWd16, g_Wd16);
    cudaGetSymbolAddress(&px16,  g_x16);

    cudaMemsetAsync(out, 0, (size_t)T * D_MODEL * sizeof(float));
    zero_kernel<<<1, 32>>>();
    router_kernel<<<T, 256>>>(x, gw, gb);
    if (out_size > T * D_MODEL) {
        loss_kernel<<<1, 32>>>(out + (size_t)T * D_MODEL, T);
    }
    const int WBLK = (int)((size_t)NE * D_MODEL * D_FF / (256 * 8));   // 8192
    const int XBLK = (int)((size_t)T * D_MODEL / (256 * 8));           // 1024
    cvt_kernel<<<WBLK, 256>>>((const float4*)Wg, (uint4*)pWg16);
    cvt_kernel<<<WBLK, 256>>>((const float4*)Wu, (uint4*)pWu16);
    cvt_kernel<<<WBLK, 256>>>((const float4*)Wd, (uint4*)pWd16);
    cvt_kernel<<<XBLK, 256>>>((const float4*)x,  (uint4*)px16);

    dim3 g1(D_FF / 64, TMAX / 128, NE);        // 32 x 16 x 8
    gu_kernel<<<g1, 256, GU_DYN>>>(bg, bu);
    dim3 g2(D_MODEL / 128, TMAX / 128, NE * 2); // 8 x 16 x 16 (split-K=2)
    dn_kernel<<<g2, 256, DN_DYN>>>(bd, out);
}

// round 16
// speedup vs baseline: 1.1699x; 1.0535x over previous
#include <cuda_runtime.h>
#include <cuda_fp16.h>
#include <math.h>
#include <stdint.h>

#define D_MODEL 1024
#define D_FF    2048
#define NE      8
#define TMAX    2048

#define BK 32
#define NSTAGE 4
#define STRA 80                       // A smem row stride bytes (128 rows)
#define STRB2 144                     // fused-GU B row stride (64 cols fp16)
#define B2_SZ (32 * STRB2)            // 4608
#define A_SZ (128 * STRA)             // 10240
#define STAGE_GU (A_SZ + 2 * B2_SZ)   // 19456 (A | Bg | Bu)
#define GU_DYN (NSTAGE * STAGE_GU)    // 77824
#define STRB 272                      // dn B row stride (128 cols fp16)
#define B_SZ (32 * STRB)              // 8704
#define STAGE_DN (A_SZ + B_SZ)        // 18944 (A | B)
#define DN_DYN (NSTAGE * STAGE_DN)    // 75776

// -------- device scratch (static; no cudaMalloc allowed) --------
__device__ int      g_count[NE];
__device__ double   g_probsum[NE];
__device__ int      g_tok[NE * TMAX];
__device__ float    g_wt[NE * TMAX];
__device__ uint4    g_Wg16[(size_t)NE * D_MODEL * D_FF / 8];
__device__ uint4    g_Wu16[(size_t)NE * D_MODEL * D_FF / 8];
__device__ uint4    g_Wd16[(size_t)NE * D_FF * D_MODEL / 8];
__device__ uint4    g_x16[(size_t)TMAX * D_MODEL / 8];
__device__ uint4    g_Hp4[(size_t)NE * TMAX * D_FF / 8];   // fp16 h

// ---------------- helpers ----------------
__device__ __forceinline__ uint32_t smem_u32(const void* p) {
    uint32_t a;
    asm("{ .reg .u64 t; cvta.to.shared.u64 t, %1; cvt.u32.u64 %0, t; }" : "=r"(a) : "l"(p));
    return a;
}
__device__ __forceinline__ uint32_t cvt2(float f0, float f1) {
    __half2 h = __floats2half2_rn(f0, f1);
    return *reinterpret_cast<uint32_t*>(&h);
}
__device__ __forceinline__ void cp16(uint32_t smem_dst, const void* gmem_src) {
    asm volatile("cp.async.cg.shared.global [%0], [%1], 16;"
                 :: "r"(smem_dst), "l"(gmem_src) : "memory");
}
#define CP_COMMIT() asm volatile("cp.async.commit_group;" ::: "memory")
#define CP_WAIT2()  asm volatile("cp.async.wait_group 2;" ::: "memory")
#define CP_WAIT1()  asm volatile("cp.async.wait_group 1;" ::: "memory")
#define CP_WAIT0()  asm volatile("cp.async.wait_group 0;" ::: "memory")
__device__ __forceinline__ void ldsm_x4(uint32_t* r, uint32_t addr) {
    asm volatile("ldmatrix.sync.aligned.m8n8.x4.shared.b16 {%0,%1,%2,%3}, [%4];"
                 : "=r"(r[0]), "=r"(r[1]), "=r"(r[2]), "=r"(r[3]) : "r"(addr));
}
__device__ __forceinline__ void ldsm_x4t(uint32_t* r, uint32_t addr) {
    asm volatile("ldmatrix.sync.aligned.m8n8.x4.trans.shared.b16 {%0,%1,%2,%3}, [%4];"
                 : "=r"(r[0]), "=r"(r[1]), "=r"(r[2]), "=r"(r[3]) : "r"(addr));
}
__device__ __forceinline__ void mma16816(float* c, const uint32_t* a, const uint32_t* b) {
    asm volatile("mma.sync.aligned.m16n8k16.row.col.f32.f16.f16.f32 "
                 "{%0,%1,%2,%3}, {%4,%5,%6,%7}, {%8,%9}, {%0,%1,%2,%3};"
                 : "+f"(c[0]), "+f"(c[1]), "+f"(c[2]), "+f"(c[3])
                 : "r"(a[0]), "r"(a[1]), "r"(a[2]), "r"(a[3]), "r"(b[0]), "r"(b[1]));
}

// ---------------------------------------------------------------------------
__global__ void zero_kernel() {
    int i = threadIdx.x;
    if (i < NE) { g_count[i] = 0; g_probsum[i] = 0.0; }
}

// Merged fp32 -> fp16 converter for the 3 weight tensors (blockIdx.z selects).
__global__ __launch_bounds__(256)
void cvtw_kernel(const float4* __restrict__ Wg, const float4* __restrict__ Wu,
                 const float4* __restrict__ Wd) {
    const float4* src = (blockIdx.z == 0) ? Wg : (blockIdx.z == 1) ? Wu : Wd;
    uint4* dst = (blockIdx.z == 0) ? g_Wg16 : (blockIdx.z == 1) ? g_Wu16 : g_Wd16;
    size_t i = (size_t)blockIdx.x * 256 + threadIdx.x;
    float4 a = src[2 * i], b = src[2 * i + 1];
    dst[i] = make_uint4(cvt2(a.x, a.y), cvt2(a.z, a.w),
                        cvt2(b.x, b.y), cvt2(b.z, b.w));
}

// Router: logits, softmax, top-2 dispatch; also converts its x row to fp16.
__global__ void router_kernel(const float* __restrict__ x,
                              const float* __restrict__ gw,
                              const float* __restrict__ gb) {
    int t    = blockIdx.x;
    int warp = threadIdx.x >> 5;
    int lane = threadIdx.x & 31;
    __shared__ float logits[NE];

    const float* xr = x + (size_t)t * D_MODEL;
    const float* w  = gw + warp * D_MODEL;
    float s = 0.f;
    for (int i = lane; i < D_MODEL; i += 32) s += xr[i] * w[i];
    #pragma unroll
    for (int o = 16; o > 0; o >>= 1) s += __shfl_down_sync(0xffffffff, s, o);
    if (lane == 0) logits[warp] = s + gb[warp];

    // convert x row to fp16 (256 threads x 4 floats = 1024)
    {
        float4 v = ((const float4*)xr)[threadIdx.x];
        uint2* xd = (uint2*)g_x16 + (size_t)t * (D_MODEL / 4);
        xd[threadIdx.x] = make_uint2(cvt2(v.x, v.y), cvt2(v.z, v.w));
    }
    __syncthreads();

    if (threadIdx.x == 0) {
        float p[NE];
        float mx = -1e30f;
        #pragma unroll
        for (int e = 0; e < NE; e++) mx = fmaxf(mx, logits[e]);
        float sum = 0.f;
        #pragma unroll
        for (int e = 0; e < NE; e++) { p[e] = expf(logits[e] - mx); sum += p[e]; }
        float inv = 1.f / sum;
        #pragma unroll
        for (int e = 0; e < NE; e++) {
            p[e] *= inv;
            atomicAdd(&g_probsum[e], (double)p[e]);
        }
        int i0 = 0;
        #pragma unroll
        for (int e = 1; e < NE; e++) if (p[e] > p[i0]) i0 = e;
        int i1 = -1;
        #pragma unroll
        for (int e = 0; e < NE; e++) {
            if (e == i0) continue;
            if (i1 < 0 || p[e] > p[i1]) i1 = e;
        }
        float v0 = p[i0], v1 = p[i1];
        float inv2 = 1.f / (v0 + v1);
        int s0 = atomicAdd(&g_count[i0], 1);
        g_tok[i0 * TMAX + s0] = t;  g_wt[i0 * TMAX + s0] = v0 * inv2;
        int s1 = atomicAdd(&g_count[i1], 1);
        g_tok[i1 * TMAX + s1] = t;  g_wt[i1 * TMAX + s1] = v1 * inv2;
    }
}

__global__ void loss_kernel(float* __restrict__ out_loss, int T) {
    if (threadIdx.x == 0) {
        const double ideal = 1.0 / NE;
        double l = 0.0;
        #pragma unroll
        for (int e = 0; e < NE; e++) {
            double mp = g_probsum[e] / (double)T + 1e-9;
            l += ideal * (log(ideal) - log(mp));
        }
        *out_loss = (float)l;
    }
}

// ---------------------------------------------------------------------------
// Fused GU: 128x64 tile of BOTH G and U, fp16 operands via cp.async 4-stage
// pipeline; epilogue silu(g)*u in-register -> fp16 Hp.
__global__ __launch_bounds__(256, 2)
void gu_kernel(const float* __restrict__ bg, const float* __restrict__ bu) {
    int e = blockIdx.z;
    int n = g_count[e];
    int rowbase = blockIdx.y * 128;
    if (rowbase >= n) return;
    int colbase = blockIdx.x * 64;

    const uint32_t* Wg16 = (const uint32_t*)g_Wg16 + (size_t)e * D_MODEL * (D_FF / 2);
    const uint32_t* Wu16 = (const uint32_t*)g_Wu16 + (size_t)e * D_MODEL * (D_FF / 2);
    const uint32_t* X16  = (const uint32_t*)g_x16;
    uint32_t*       Hp   = (uint32_t*)g_Hp4 + (size_t)e * TMAX * (D_FF / 2);

    extern __shared__ char sm[];
    __shared__ int toks[128];
    uint32_t sbase = smem_u32(sm);

    int tid = threadIdx.x, lane = tid & 31, wid = tid >> 5;
    int wm = wid >> 1, wn = wid & 1;

    if (tid < 128) {
        int r = rowbase + tid;
        toks[tid] = g_tok[e * TMAX + (r < n ? r : n - 1)];
    }
    __syncthreads();

    auto issue = [&](int k0, int buf) {
        uint32_t stu = sbase + buf * STAGE_GU;
        #pragma unroll
        for (int it = 0; it < 2; it++) {
            int c = tid + it * 256;
            int row = c >> 2, seg = c & 3;
            const uint32_t* src = X16 + (size_t)toks[row] * (D_MODEL / 2) + (k0 >> 1) + seg * 4;
            cp16(stu + row * STRA + seg * 16, src);
        }
        {
            int row = tid >> 3, seg = tid & 7;
            size_t bo = (size_t)(k0 + row) * (D_FF / 2) + (colbase >> 1) + seg * 4;
            cp16(stu + A_SZ + row * STRB2 + seg * 16, Wg16 + bo);
            cp16(stu + A_SZ + B2_SZ + row * STRB2 + seg * 16, Wu16 + bo);
        }
        CP_COMMIT();
    };

    float accG[2][4][4] = {}, accU[2][4][4] = {};
    int ar = lane & 15, ac = lane >> 4;          // A ldsm addr parts
    int kr = lane & 7,  sel = lane >> 3;         // B ldsm addr parts

    auto compute = [&](int buf) {
        uint32_t Ah  = sbase + buf * STAGE_GU;
        uint32_t BGh = Ah + A_SZ;
        uint32_t BUh = BGh + B2_SZ;
        #pragma unroll
        for (int ks = 0; ks < 2; ks++) {
            uint32_t ah[2][4], bgh[8], buh[8];
            #pragma unroll
            for (int mt = 0; mt < 2; mt++) {
                uint32_t off = (uint32_t)((wm * 32 + mt * 16 + ar) * STRA + (ks * 16 + ac * 8) * 2);
                ldsm_x4(ah[mt], Ah + off);
            }
            #pragma unroll
            for (int nt2 = 0; nt2 < 2; nt2++) {
                int rowk = ks * 16 + (sel & 1) * 8 + kr;
                int coln = wn * 32 + nt2 * 16 + (sel >> 1) * 8;
                uint32_t off = (uint32_t)(rowk * STRB2 + coln * 2);
                ldsm_x4t(&bgh[nt2 * 4], BGh + off);
                ldsm_x4t(&buh[nt2 * 4], BUh + off);
            }
            #pragma unroll
            for (int mt = 0; mt < 2; mt++)
                #pragma unroll
                for (int nt = 0; nt < 4; nt++) {
                    int bo = (nt >> 1) * 4 + (nt & 1) * 2;
                    mma16816(accG[mt][nt], ah[mt], &bgh[bo]);
                    mma16816(accU[mt][nt], ah[mt], &buh[bo]);
                }
        }
    };

    const int NIT = D_MODEL / BK;   // 32
    issue(0, 0);
    issue(BK, 1);
    issue(2 * BK, 2);
    for (int i = 0; i < NIT; i++) {
        if (i < NIT - 2)       { CP_WAIT2(); }
        else if (i == NIT - 2) { CP_WAIT1(); }
        else                   { CP_WAIT0(); }
        __syncthreads();
        if (i + NSTAGE - 1 < NIT) issue((i + NSTAGE - 1) * BK, (i + NSTAGE - 1) % NSTAGE);
        compute(i % NSTAGE);
    }

    // epilogue: h = silu(g+bg)*(u+bu), write fp16 half2-packed Hp
    const float* bgp = bg + e * D_FF + colbase;
    const float* bup = bu + e * D_FF + colbase;
    #pragma unroll
    for (int mt = 0; mt < 2; mt++) {
        int r0 = rowbase + wm * 32 + mt * 16 + (lane >> 2);
        #pragma unroll
        for (int nt = 0; nt < 4; nt++) {
            int c = wn * 32 + nt * 8 + (lane & 3) * 2;
            float bg0 = bgp[c], bg1 = bgp[c + 1];
            float bu0 = bup[c], bu1 = bup[c + 1];
            #pragma unroll
            for (int half = 0; half < 2; half++) {
                int r = r0 + half * 8;
                if (r >= n) continue;
                float g0 = accG[mt][nt][half * 2]     + bg0;
                float g1 = accG[mt][nt][half * 2 + 1] + bg1;
                float u0 = accU[mt][nt][half * 2]     + bu0;
                float u1 = accU[mt][nt][half * 2 + 1] + bu1;
                float h0 = g0 / (1.f + __expf(-g0)) * u0;
                float h1 = g1 / (1.f + __expf(-g1)) * u1;
                Hp[(size_t)r * (D_FF / 2) + (colbase + c) / 2] = cvt2(h0, h1);
            }
        }
    }
}

// ---------------------------------------------------------------------------
// Down: out[t] += w * ( H @ Wd + bd ), fp16 via cp.async 4-stage pipeline.
// No split-K: full K=2048 per CTA (256 active CTAs ~= one wave, atomics halved).
__global__ __launch_bounds__(256, 2)
void dn_kernel(const float* __restrict__ bd, float* __restrict__ out) {
    int e = blockIdx.z;
    int n = g_count[e];
    int rowbase = blockIdx.y * 128;
    if (rowbase >= n) return;
    int colbase = blockIdx.x * 128;

    const uint32_t* Wd16 = (const uint32_t*)g_Wd16 + (size_t)e * D_FF * (D_MODEL / 2);
    const uint32_t* Hp   = (const uint32_t*)g_Hp4 + (size_t)e * TMAX * (D_FF / 2);

    extern __shared__ char sm[];
    uint32_t sbase = smem_u32(sm);

    int tid = threadIdx.x, lane = tid & 31, wid = tid >> 5;
    int wm = wid >> 2, wn = wid & 3;

    auto issue = [&](int k0, int buf) {
        uint32_t stu = sbase + buf * STAGE_DN;
        #pragma unroll
        for (int it = 0; it < 2; it++) {
            int c = tid + it * 256;
            int row = c >> 2, seg = c & 3;
            int r = rowbase + row; if (r >= n) r = n - 1;
            const uint32_t* src = Hp + (size_t)r * (D_FF / 2) + (k0 >> 1) + seg * 4;
            cp16(stu + row * STRA + seg * 16, src);
        }
        #pragma unroll
        for (int it = 0; it < 2; it++) {
            int c = tid + it * 256;
            int row = c >> 4, seg = c & 15;
            const uint32_t* src = Wd16 + (size_t)(k0 + row) * (D_MODEL / 2) + (colbase >> 1) + seg * 4;
            cp16(stu + A_SZ + row * STRB + seg * 16, src);
        }
        CP_COMMIT();
    };

    float acc[4][4][4] = {};
    int ar = lane & 15, ac = lane >> 4;
    int kr = lane & 7,  sel = lane >> 3;

    auto compute = [&](int buf) {
        uint32_t Ah = sbase + buf * STAGE_DN;
        uint32_t Bh = Ah + A_SZ;
        #pragma unroll
        for (int ks = 0; ks < 2; ks++) {
            uint32_t ah[4][4], bh[8];
            #pragma unroll
            for (int mt = 0; mt < 4; mt++) {
                uint32_t off = (uint32_t)((wm * 64 + mt * 16 + ar) * STRA + (ks * 16 + ac * 8) * 2);
                ldsm_x4(ah[mt], Ah + off);
            }
            #pragma unroll
            for (int nt2 = 0; nt2 < 2; nt2++) {
                int rowk = ks * 16 + (sel & 1) * 8 + kr;
                int coln = wn * 32 + nt2 * 16 + (sel >> 1) * 8;
                uint32_t off = (uint32_t)(rowk * STRB + coln * 2);
                ldsm_x4t(&bh[nt2 * 4], Bh + off);
            }
            #pragma unroll
            for (int mt = 0; mt < 4; mt++)
                #pragma unroll
                for (int nt = 0; nt < 4; nt++) {
                    const uint32_t* bhp = &bh[(nt >> 1) * 4 + (nt & 1) * 2];
                    mma16816(acc[mt][nt], ah[mt], bhp);
                }
        }
    };

    const int NIT = D_FF / BK;   // 64
    issue(0, 0);
    issue(BK, 1);
    issue(2 * BK, 2);
    for (int i = 0; i < NIT; i++) {
        if (i < NIT - 2)       { CP_WAIT2(); }
        else if (i == NIT - 2) { CP_WAIT1(); }
        else                   { CP_WAIT0(); }
        __syncthreads();
        if (i + NSTAGE - 1 < NIT) issue((i + NSTAGE - 1) * BK, (i + NSTAGE - 1) % NSTAGE);
        compute(i % NSTAGE);
    }

    // epilogue: + bd, * combine weight, atomic scatter into out
    #pragma unroll
    for (int mt = 0; mt < 4; mt++) {
        int r0 = rowbase + wm * 64 + mt * 16 + (lane >> 2);
        #pragma unroll
        for (int nt = 0; nt < 4; nt++) {
            int c = colbase + wn * 32 + nt * 8 + (lane & 3) * 2;
            float b0 = bd[e * D_MODEL + c], b1 = bd[e * D_MODEL + c + 1];
            if (r0 < n) {
                int t = g_tok[e * TMAX + r0];
                float w = g_wt[e * TMAX + r0];
                atomicAdd(&out[(size_t)t * D_MODEL + c],     w * (acc[mt][nt][0] + b0));
                atomicAdd(&out[(size_t)t * D_MODEL + c + 1], w * (acc[mt][nt][1] + b1));
            }
            if (r0 + 8 < n) {
                int t = g_tok[e * TMAX + r0 + 8];
                float w = g_wt[e * TMAX + r0 + 8];
                atomicAdd(&out[(size_t)t * D_MODEL + c],     w * (acc[mt][nt][2] + b0));
                atomicAdd(&out[(size_t)t * D_MODEL + c + 1], w * (acc[mt][nt][3] + b1));
            }
        }
    }
}

// ---------------------------------------------------------------------------
extern "C" void kernel_launch(void* const* d_in, const int* in_sizes, int n_in,
                              void* d_out, int out_size) {
    const float* x  = (const float*)d_in[0];
    const float* gw = (const float*)d_in[1];
    const float* gb = (const float*)d_in[2];
    const float* Wg = (const float*)d_in[3];
    const float* bg = (const float*)d_in[4];
    const float* Wu = (const float*)d_in[5];
    const float* bu = (const float*)d_in[6];
    const float* Wd = (const float*)d_in[7];
    const float* bd = (const float*)d_in[8];
    float* out = (float*)d_out;

    int T = in_sizes[0] / D_MODEL;   // 2048

    cudaFuncSetAttribute(gu_kernel, cudaFuncAttributeMaxDynamicSharedMemorySize, GU_DYN);
    cudaFuncSetAttribute(dn_kernel, cudaFuncAttributeMaxDynamicSharedMemorySize, DN_DYN);

    cudaMemsetAsync(out, 0, (size_t)T * D_MODEL * sizeof(float));
    zero_kernel<<<1, 32>>>();
    router_kernel<<<T, 256>>>(x, gw, gb);     // also emits x16
    if (out_size > T * D_MODEL) {
        loss_kernel<<<1, 32>>>(out + (size_t)T * D_MODEL, T);
    }
    // merged weight fp32->fp16 conversion
    const int WBLK = (int)((size_t)NE * D_MODEL * D_FF / (256 * 8));   // 8192
    dim3 gc(WBLK, 1, 3);
    cvtw_kernel<<<gc, 256>>>((const float4*)Wg, (const float4*)Wu, (const float4*)Wd);

    dim3 g1(D_FF / 64, TMAX / 128, NE);       // 32 x 16 x 8
    gu_kernel<<<g1, 256, GU_DYN>>>(bg, bu);
    dim3 g2(D_MODEL / 128, TMAX / 128, NE);   // 8 x 16 x 8 (no split-K)
    dn_kernel<<<g2, 256, DN_DYN>>>(bd, out);
}

// round 17
// speedup vs baseline: 1.2024x; 1.0278x over previous
#include <cuda_runtime.h>
#include <cuda_fp16.h>
#include <math.h>
#include <stdint.h>

#define D_MODEL 1024
#define D_FF    2048
#define NE      8
#define TMAX    2048

#define BK 64
#define NSTAGE 2
#define STRA 144                      // A smem row stride bytes (128 rows x 128B data + 16 pad)
#define A_SZ (128 * STRA)             // 18432
#define STRB2 144                     // fused-GU B row stride (64 cols fp16 = 128B + pad)
#define B2_SZ (64 * STRB2)            // 9216
#define STAGE_GU (A_SZ + 2 * B2_SZ)   // 36864 (A | Bg | Bu)
#define GU_DYN (NSTAGE * STAGE_GU)    // 73728
#define STRB 272                      // dn B row stride (128 cols fp16 = 256B + pad)
#define B_SZ (64 * STRB)              // 17408
#define STAGE_DN (A_SZ + B_SZ)        // 35840 (A | B)
#define DN_DYN (NSTAGE * STAGE_DN)    // 71680

// -------- device scratch (static; no cudaMalloc allowed) --------
__device__ int      g_count[NE];
__device__ double   g_probsum[NE];
__device__ int      g_tok[NE * TMAX];
__device__ float    g_wt[NE * TMAX];
__device__ uint4    g_Wg16[(size_t)NE * D_MODEL * D_FF / 8];
__device__ uint4    g_Wu16[(size_t)NE * D_MODEL * D_FF / 8];
__device__ uint4    g_Wd16[(size_t)NE * D_FF * D_MODEL / 8];
__device__ uint4    g_x16[(size_t)TMAX * D_MODEL / 8];
__device__ uint4    g_Hp4[(size_t)NE * TMAX * D_FF / 8];   // fp16 h

// ---------------- helpers ----------------
__device__ __forceinline__ uint32_t smem_u32(const void* p) {
    uint32_t a;
    asm("{ .reg .u64 t; cvta.to.shared.u64 t, %1; cvt.u32.u64 %0, t; }" : "=r"(a) : "l"(p));
    return a;
}
__device__ __forceinline__ uint32_t cvt2(float f0, float f1) {
    __half2 h = __floats2half2_rn(f0, f1);
    return *reinterpret_cast<uint32_t*>(&h);
}
__device__ __forceinline__ void cp16(uint32_t smem_dst, const void* gmem_src) {
    asm volatile("cp.async.cg.shared.global [%0], [%1], 16;"
                 :: "r"(smem_dst), "l"(gmem_src) : "memory");
}
#define CP_COMMIT() asm volatile("cp.async.commit_group;" ::: "memory")
#define CP_WAIT0()  asm volatile("cp.async.wait_group 0;" ::: "memory")
__device__ __forceinline__ void ldsm_x4(uint32_t* r, uint32_t addr) {
    asm volatile("ldmatrix.sync.aligned.m8n8.x4.shared.b16 {%0,%1,%2,%3}, [%4];"
                 : "=r"(r[0]), "=r"(r[1]), "=r"(r[2]), "=r"(r[3]) : "r"(addr));
}
__device__ __forceinline__ void ldsm_x4t(uint32_t* r, uint32_t addr) {
    asm volatile("ldmatrix.sync.aligned.m8n8.x4.trans.shared.b16 {%0,%1,%2,%3}, [%4];"
                 : "=r"(r[0]), "=r"(r[1]), "=r"(r[2]), "=r"(r[3]) : "r"(addr));
}
__device__ __forceinline__ void mma16816(float* c, const uint32_t* a, const uint32_t* b) {
    asm volatile("mma.sync.aligned.m16n8k16.row.col.f32.f16.f16.f32 "
                 "{%0,%1,%2,%3}, {%4,%5,%6,%7}, {%8,%9}, {%0,%1,%2,%3};"
                 : "+f"(c[0]), "+f"(c[1]), "+f"(c[2]), "+f"(c[3])
                 : "r"(a[0]), "r"(a[1]), "r"(a[2]), "r"(a[3]), "r"(b[0]), "r"(b[1]));
}

// ---------------------------------------------------------------------------
__global__ void zero_kernel() {
    int i = threadIdx.x;
    if (i < NE) { g_count[i] = 0; g_probsum[i] = 0.0; }
}

// Merged fp32 -> fp16 converter for the 3 weight tensors (blockIdx.z selects).
__global__ __launch_bounds__(256)
void cvtw_kernel(const float4* __restrict__ Wg, const float4* __restrict__ Wu,
                 const float4* __restrict__ Wd) {
    const float4* src = (blockIdx.z == 0) ? Wg : (blockIdx.z == 1) ? Wu : Wd;
    uint4* dst = (blockIdx.z == 0) ? g_Wg16 : (blockIdx.z == 1) ? g_Wu16 : g_Wd16;
    size_t i = (size_t)blockIdx.x * 256 + threadIdx.x;
    float4 a = src[2 * i], b = src[2 * i + 1];
    dst[i] = make_uint4(cvt2(a.x, a.y), cvt2(a.z, a.w),
                        cvt2(b.x, b.y), cvt2(b.z, b.w));
}

// Router: logits, softmax, top-2 dispatch; also converts its x row to fp16.
__global__ void router_kernel(const float* __restrict__ x,
                              const float* __restrict__ gw,
                              const float* __restrict__ gb) {
    int t    = blockIdx.x;
    int warp = threadIdx.x >> 5;
    int lane = threadIdx.x & 31;
    __shared__ float logits[NE];

    const float* xr = x + (size_t)t * D_MODEL;
    const float* w  = gw + warp * D_MODEL;
    float s = 0.f;
    for (int i = lane; i < D_MODEL; i += 32) s += xr[i] * w[i];
    #pragma unroll
    for (int o = 16; o > 0; o >>= 1) s += __shfl_down_sync(0xffffffff, s, o);
    if (lane == 0) logits[warp] = s + gb[warp];

    // convert x row to fp16 (256 threads x 4 floats = 1024)
    {
        float4 v = ((const float4*)xr)[threadIdx.x];
        uint2* xd = (uint2*)g_x16 + (size_t)t * (D_MODEL / 4);
        xd[threadIdx.x] = make_uint2(cvt2(v.x, v.y), cvt2(v.z, v.w));
    }
    __syncthreads();

    if (threadIdx.x == 0) {
        float p[NE];
        float mx = -1e30f;
        #pragma unroll
        for (int e = 0; e < NE; e++) mx = fmaxf(mx, logits[e]);
        float sum = 0.f;
        #pragma unroll
        for (int e = 0; e < NE; e++) { p[e] = expf(logits[e] - mx); sum += p[e]; }
        float inv = 1.f / sum;
        #pragma unroll
        for (int e = 0; e < NE; e++) {
            p[e] *= inv;
            atomicAdd(&g_probsum[e], (double)p[e]);
        }
        int i0 = 0;
        #pragma unroll
        for (int e = 1; e < NE; e++) if (p[e] > p[i0]) i0 = e;
        int i1 = -1;
        #pragma unroll
        for (int e = 0; e < NE; e++) {
            if (e == i0) continue;
            if (i1 < 0 || p[e] > p[i1]) i1 = e;
        }
        float v0 = p[i0], v1 = p[i1];
        float inv2 = 1.f / (v0 + v1);
        int s0 = atomicAdd(&g_count[i0], 1);
        g_tok[i0 * TMAX + s0] = t;  g_wt[i0 * TMAX + s0] = v0 * inv2;
        int s1 = atomicAdd(&g_count[i1], 1);
        g_tok[i1 * TMAX + s1] = t;  g_wt[i1 * TMAX + s1] = v1 * inv2;
    }
}

__global__ void loss_kernel(float* __restrict__ out_loss, int T) {
    if (threadIdx.x == 0) {
        const double ideal = 1.0 / NE;
        double l = 0.0;
        #pragma unroll
        for (int e = 0; e < NE; e++) {
            double mp = g_probsum[e] / (double)T + 1e-9;
            l += ideal * (log(ideal) - log(mp));
        }
        *out_loss = (float)l;
    }
}

// ---------------------------------------------------------------------------
// Fused GU: 128x64 tile of BOTH G and U, fp16 operands, BK=64, 2-stage
// cp.async double buffer; epilogue silu(g)*u in-register -> fp16 Hp.
__global__ __launch_bounds__(256, 2)
void gu_kernel(const float* __restrict__ bg, const float* __restrict__ bu) {
    int e = blockIdx.z;
    int n = g_count[e];
    int rowbase = blockIdx.y * 128;
    if (rowbase >= n) return;
    int colbase = blockIdx.x * 64;

    const uint32_t* Wg16 = (const uint32_t*)g_Wg16 + (size_t)e * D_MODEL * (D_FF / 2);
    const uint32_t* Wu16 = (const uint32_t*)g_Wu16 + (size_t)e * D_MODEL * (D_FF / 2);
    const uint32_t* X16  = (const uint32_t*)g_x16;
    uint32_t*       Hp   = (uint32_t*)g_Hp4 + (size_t)e * TMAX * (D_FF / 2);

    extern __shared__ char sm[];
    __shared__ int toks[128];
    uint32_t sbase = smem_u32(sm);

    int tid = threadIdx.x, lane = tid & 31, wid = tid >> 5;
    int wm = wid >> 1, wn = wid & 1;

    if (tid < 128) {
        int r = rowbase + tid;
        toks[tid] = g_tok[e * TMAX + (r < n ? r : n - 1)];
    }
    __syncthreads();

    auto issue = [&](int k0, int buf) {
        uint32_t stu = sbase + buf * STAGE_GU;
        // A: 128 rows x 128B = 1024 chunks of 16B (4/thread)
        #pragma unroll
        for (int it = 0; it < 4; it++) {
            int c = tid + it * 256;
            int row = c >> 3, seg = c & 7;
            const uint32_t* src = X16 + (size_t)toks[row] * (D_MODEL / 2) + (k0 >> 1) + seg * 4;
            cp16(stu + row * STRA + seg * 16, src);
        }
        // Bg/Bu: 64 rows x 128B = 512 chunks each (2/thread each)
        #pragma unroll
        for (int it = 0; it < 2; it++) {
            int c = tid + it * 256;
            int row = c >> 3, seg = c & 7;
            size_t bo = (size_t)(k0 + row) * (D_FF / 2) + (colbase >> 1) + seg * 4;
            cp16(stu + A_SZ + row * STRB2 + seg * 16, Wg16 + bo);
            cp16(stu + A_SZ + B2_SZ + row * STRB2 + seg * 16, Wu16 + bo);
        }
        CP_COMMIT();
    };

    float accG[2][4][4] = {}, accU[2][4][4] = {};
    int ar = lane & 15, ac = lane >> 4;          // A ldsm addr parts
    int kr = lane & 7,  sel = lane >> 3;         // B ldsm addr parts

    auto compute = [&](int buf) {
        uint32_t Ah  = sbase + buf * STAGE_GU;
        uint32_t BGh = Ah + A_SZ;
        uint32_t BUh = BGh + B2_SZ;
        #pragma unroll
        for (int ks = 0; ks < 4; ks++) {
            uint32_t ah[2][4], bgh[8], buh[8];
            #pragma unroll
            for (int mt = 0; mt < 2; mt++) {
                uint32_t off = (uint32_t)((wm * 32 + mt * 16 + ar) * STRA + (ks * 16 + ac * 8) * 2);
                ldsm_x4(ah[mt], Ah + off);
            }
            #pragma unroll
            for (int nt2 = 0; nt2 < 2; nt2++) {
                int rowk = ks * 16 + (sel & 1) * 8 + kr;
                int coln = wn * 32 + nt2 * 16 + (sel >> 1) * 8;
                uint32_t off = (uint32_t)(rowk * STRB2 + coln * 2);
                ldsm_x4t(&bgh[nt2 * 4], BGh + off);
                ldsm_x4t(&buh[nt2 * 4], BUh + off);
            }
            #pragma unroll
            for (int mt = 0; mt < 2; mt++)
                #pragma unroll
                for (int nt = 0; nt < 4; nt++) {
                    int bo = (nt >> 1) * 4 + (nt & 1) * 2;
                    mma16816(accG[mt][nt], ah[mt], &bgh[bo]);
                    mma16816(accU[mt][nt], ah[mt], &buh[bo]);
                }
        }
    };

    const int NIT = D_MODEL / BK;   // 16
    issue(0, 0);
    for (int i = 0; i < NIT; i++) {
        CP_WAIT0();
        __syncthreads();
        if (i + 1 < NIT) issue((i + 1) * BK, (i + 1) & 1);
        compute(i & 1);
    }

    // epilogue: h = silu(g+bg)*(u+bu), write fp16 half2-packed Hp
    const float* bgp = bg + e * D_FF + colbase;
    const float* bup = bu + e * D_FF + colbase;
    #pragma unroll
    for (int mt = 0; mt < 2; mt++) {
        int r0 = rowbase + wm * 32 + mt * 16 + (lane >> 2);
        #pragma unroll
        for (int nt = 0; nt < 4; nt++) {
            int c = wn * 32 + nt * 8 + (lane & 3) * 2;
            float bg0 = bgp[c], bg1 = bgp[c + 1];
            float bu0 = bup[c], bu1 = bup[c + 1];
            #pragma unroll
            for (int half = 0; half < 2; half++) {
                int r = r0 + half * 8;
                if (r >= n) continue;
                float g0 = accG[mt][nt][half * 2]     + bg0;
                float g1 = accG[mt][nt][half * 2 + 1] + bg1;
                float u0 = accU[mt][nt][half * 2]     + bu0;
                float u1 = accU[mt][nt][half * 2 + 1] + bu1;
                float h0 = g0 / (1.f + __expf(-g0)) * u0;
                float h1 = g1 / (1.f + __expf(-g1)) * u1;
                Hp[(size_t)r * (D_FF / 2) + (colbase + c) / 2] = cvt2(h0, h1);
            }
        }
    }
}

// ---------------------------------------------------------------------------
// Down: out[t] += w * ( H @ Wd + bd ), fp16, BK=64, 2-stage double buffer.
__global__ __launch_bounds__(256, 2)
void dn_kernel(const float* __restrict__ bd, float* __restrict__ out) {
    int e = blockIdx.z;
    int n = g_count[e];
    int rowbase = blockIdx.y * 128;
    if (rowbase >= n) return;
    int colbase = blockIdx.x * 128;

    const uint32_t* Wd16 = (const uint32_t*)g_Wd16 + (size_t)e * D_FF * (D_MODEL / 2);
    const uint32_t* Hp   = (const uint32_t*)g_Hp4 + (size_t)e * TMAX * (D_FF / 2);

    extern __shared__ char sm[];
    uint32_t sbase = smem_u32(sm);

    int tid = threadIdx.x, lane = tid & 31, wid = tid >> 5;
    int wm = wid >> 2, wn = wid & 3;

    auto issue = [&](int k0, int buf) {
        uint32_t stu = sbase + buf * STAGE_DN;
        // A: 128 rows x 128B = 1024 chunks (4/thread)
        #pragma unroll
        for (int it = 0; it < 4; it++) {
            int c = tid + it * 256;
            int row = c >> 3, seg = c & 7;
            int r = rowbase + row; if (r >= n) r = n - 1;
            const uint32_t* src = Hp + (size_t)r * (D_FF / 2) + (k0 >> 1) + seg * 4;
            cp16(stu + row * STRA + seg * 16, src);
        }
        // B: 64 rows x 256B = 1024 chunks (4/thread)
        #pragma unroll
        for (int it = 0; it < 4; it++) {
            int c = tid + it * 256;
            int row = c >> 4, seg = c & 15;
            const uint32_t* src = Wd16 + (size_t)(k0 + row) * (D_MODEL / 2) + (colbase >> 1) + seg * 4;
            cp16(stu + A_SZ + row * STRB + seg * 16, src);
        }
        CP_COMMIT();
    };

    float acc[4][4][4] = {};
    int ar = lane & 15, ac = lane >> 4;
    int kr = lane & 7,  sel = lane >> 3;

    auto compute = [&](int buf) {
        uint32_t Ah = sbase + buf * STAGE_DN;
        uint32_t Bh = Ah + A_SZ;
        #pragma unroll
        for (int ks = 0; ks < 4; ks++) {
            uint32_t ah[4][4], bh[8];
            #pragma unroll
            for (int mt = 0; mt < 4; mt++) {
                uint32_t off = (uint32_t)((wm * 64 + mt * 16 + ar) * STRA + (ks * 16 + ac * 8) * 2);
                ldsm_x4(ah[mt], Ah + off);
            }
            #pragma unroll
            for (int nt2 = 0; nt2 < 2; nt2++) {
                int rowk = ks * 16 + (sel & 1) * 8 + kr;
                int coln = wn * 32 + nt2 * 16 + (sel >> 1) * 8;
                uint32_t off = (uint32_t)(rowk * STRB + coln * 2);
                ldsm_x4t(&bh[nt2 * 4], Bh + off);
            }
            #pragma unroll
            for (int mt = 0; mt < 4; mt++)
                #pragma unroll
                for (int nt = 0; nt < 4; nt++) {
                    const uint32_t* bhp = &bh[(nt >> 1) * 4 + (nt & 1) * 2];
                    mma16816(acc[mt][nt], ah[mt], bhp);
                }
        }
    };

    const int NIT = D_FF / BK;   // 32
    issue(0, 0);
    for (int i = 0; i < NIT; i++) {
        CP_WAIT0();
        __syncthreads();
        if (i + 1 < NIT) issue((i + 1) * BK, (i + 1) & 1);
        compute(i & 1);
    }

    // epilogue: + bd, * combine weight, atomic scatter into out
    #pragma unroll
    for (int mt = 0; mt < 4; mt++) {
        int r0 = rowbase + wm * 64 + mt * 16 + (lane >> 2);
        #pragma unroll
        for (int nt = 0; nt < 4; nt++) {
            int c = colbase + wn * 32 + nt * 8 + (lane & 3) * 2;
            float b0 = bd[e * D_MODEL + c], b1 = bd[e * D_MODEL + c + 1];
            if (r0 < n) {
                int t = g_tok[e * TMAX + r0];
                float w = g_wt[e * TMAX + r0];
                atomicAdd(&out[(size_t)t * D_MODEL + c],     w * (acc[mt][nt][0] + b0));
                atomicAdd(&out[(size_t)t * D_MODEL + c + 1], w * (acc[mt][nt][1] + b1));
            }
            if (r0 + 8 < n) {
                int t = g_tok[e * TMAX + r0 + 8];
                float w = g_wt[e * TMAX + r0 + 8];
                atomicAdd(&out[(size_t)t * D_MODEL + c],     w * (acc[mt][nt][2] + b0));
                atomicAdd(&out[(size_t)t * D_MODEL + c + 1], w * (acc[mt][nt][3] + b1));
            }
        }
    }
}

// ---------------------------------------------------------------------------
extern "C" void kernel_launch(void* const* d_in, const int* in_sizes, int n_in,
                              void* d_out, int out_size) {
    const float* x  = (const float*)d_in[0];
    const float* gw = (const float*)d_in[1];
    const float* gb = (const float*)d_in[2];
    const float* Wg = (const float*)d_in[3];
    const float* bg = (const float*)d_in[4];
    const float* Wu = (const float*)d_in[5];
    const float* bu = (const float*)d_in[6];
    const float* Wd = (const float*)d_in[7];
    const float* bd = (const float*)d_in[8];
    float* out = (float*)d_out;

    int T = in_sizes[0] / D_MODEL;   // 2048

    cudaFuncSetAttribute(gu_kernel, cudaFuncAttributeMaxDynamicSharedMemorySize, GU_DYN);
    cudaFuncSetAttribute(dn_kernel, cudaFuncAttributeMaxDynamicSharedMemorySize, DN_DYN);

    cudaMemsetAsync(out, 0, (size_t)T * D_MODEL * sizeof(float));
    zero_kernel<<<1, 32>>>();
    router_kernel<<<T, 256>>>(x, gw, gb);     // also emits x16
    if (out_size > T * D_MODEL) {
        loss_kernel<<<1, 32>>>(out + (size_t)T * D_MODEL, T);
    }
    // merged weight fp32->fp16 conversion
    const int WBLK = (int)((size_t)NE * D_MODEL * D_FF / (256 * 8));   // 8192
    dim3 gc(WBLK, 1, 3);
    cvtw_kernel<<<gc, 256>>>((const float4*)Wg, (const float4*)Wu, (const float4*)Wd);

    dim3 g1(D_FF / 64, TMAX / 128, NE);       // 32 x 16 x 8
    gu_kernel<<<g1, 256, GU_DYN>>>(bg, bu);
    dim3 g2(D_MODEL / 128, TMAX / 128, NE);   // 8 x 16 x 8
    dn_kernel<<<g2, 256, DN_DYN>>>(bd, out);
}